// round 14
// baseline (speedup 1.0000x reference)
#include <cuda_runtime.h>
#include <cuda_fp16.h>
#include <cstdint>

#define DZ 32
#define L2E 1.4426950408889634f

// ---------------------------------------------------------------------------
// Static device scratch (no runtime allocation allowed)
// g_mu_hi/lo: per mu row n: 16 dwords (half2 k-pairs), reordered so that
// position 4*(p&3)+(p>>2) holds k-pair p  ->  thread l4 reads k-pairs
// {l4, l4+4, l4+8, l4+12} as ONE contiguous 16-byte access.
// hi staged via cp.async->smem (hot path); lo fetched by LDG only on accept.
// Values: w = mu_hat * kappa * log2e, fp16 hi + fp16 residual lo.
// ---------------------------------------------------------------------------
__device__ uint32_t g_mu_hi[4096 * 16];
__device__ uint32_t g_mu_lo[4096 * 16];
__device__ float g_partials[1024];
__device__ int   g_ticket;            // zero-init; reset by last block each run

static __device__ __forceinline__ uint32_t s2u(const void* p) {
    uint32_t a;
    asm("{ .reg .u64 t; cvta.to.shared.u64 t, %1; cvt.u32.u64 %0, t; }" : "=r"(a) : "l"(p));
    return a;
}
static __device__ __forceinline__ void cp16(uint32_t saddr, const void* gaddr) {
    asm volatile("cp.async.cg.shared.global [%0], [%1], 16;"
                 :: "r"(saddr), "l"(__cvta_generic_to_global(gaddr)) : "memory");
}
static __device__ __forceinline__ float ex2f(float x) {
    float r; asm("ex2.approx.f32 %0, %1;" : "=f"(r) : "f"(x)); return r;
}
// m16n8k16 fp16 MMA, f32 accumulate
static __device__ __forceinline__ void mma16(float* d, const uint32_t* a,
                                             uint32_t b0, uint32_t b1) {
    asm volatile(
        "mma.sync.aligned.m16n8k16.row.col.f32.f16.f16.f32 "
        "{%0,%1,%2,%3},{%4,%5,%6,%7},{%8,%9},{%0,%1,%2,%3};"
        : "+f"(d[0]), "+f"(d[1]), "+f"(d[2]), "+f"(d[3])
        : "r"(a[0]), "r"(a[1]), "r"(a[2]), "r"(a[3]), "r"(b0), "r"(b1));
}
// m16n8k16 fp16 MMA, fp16 accumulate (prefilter)
static __device__ __forceinline__ void mma16h(uint32_t* d, const uint32_t* a,
                                              uint32_t b0, uint32_t b1) {
    asm volatile(
        "mma.sync.aligned.m16n8k16.row.col.f16.f16.f16.f16 "
        "{%0,%1},{%2,%3,%4,%5},{%6,%7},{%0,%1};"
        : "+r"(d[0]), "+r"(d[1])
        : "r"(a[0]), "r"(a[1]), "r"(a[2]), "r"(a[3]), "r"(b0), "r"(b1));
}

// ---------------------------------------------------------------------------
// Prep: normalize mu, scale by kappa*log2e, fp16 hi/lo split, store planes
// with the k-pair interleave. One warp per row.
// ---------------------------------------------------------------------------
__global__ void vmf_prep_mu(const float* __restrict__ mu,
                            const float* __restrict__ kap_p, int B)
{
    const int n = (blockIdx.x * blockDim.x + threadIdx.x) >> 5;
    const int k = threadIdx.x & 31;
    if (n >= B) return;

    float v = __ldg(mu + (size_t)n * DZ + k);
    float ss = v * v;
    #pragma unroll
    for (int o = 16; o > 0; o >>= 1) ss += __shfl_xor_sync(0xFFFFFFFFu, ss, o);
    float r = rsqrtf(ss);
    r = r * fmaf(-0.5f * ss * r, r, 1.5f);           // Newton -> ~1e-7 rel
    float w = v * r * (__ldg(kap_p) * L2E);

    __half h = __float2half_rn(w);
    __half l = __float2half_rn(w - __half2float(h));
    uint32_t hs = (uint32_t)__half_as_ushort(h);
    uint32_t ls = (uint32_t)__half_as_ushort(l);

    uint32_t h0 = __shfl_sync(0xFFFFFFFFu, hs, (k * 2) & 31);
    uint32_t h1 = __shfl_sync(0xFFFFFFFFu, hs, (k * 2 + 1) & 31);
    uint32_t l0 = __shfl_sync(0xFFFFFFFFu, ls, (k * 2) & 31);
    uint32_t l1 = __shfl_sync(0xFFFFFFFFu, ls, (k * 2 + 1) & 31);
    if (k < 16) {
        const int pos = 4 * (k & 3) + (k >> 2);      // k-pair interleave
        g_mu_hi[n * 16 + pos] = h0 | (h1 << 16);
        g_mu_lo[n * 16 + pos] = l0 | (l1 << 16);
    }
}

// ---------------------------------------------------------------------------
// Main: 128 z rows/CTA (8 warps x ONE m16 tile each), grid 512.
// mu hi-plane streamed in 64-row chunks via cp.async x2 (4KB each).
// Hot path per 16x8 block: ONE LDS.128 (hi) + 2 fp16-accum MMAs +
// hmax2/hmax/hgt vs min-threshold + vote. Accepted (~9%): ONE LDG.128 (lo,
// straight from L2) + 6 f32-accum MMAs + ex2-accumulate.
// Last block reduces partials -> out.
// ---------------------------------------------------------------------------
__global__ void __launch_bounds__(256, 4) vmf_main(
    const float* __restrict__ mu, const float* __restrict__ z,
    const float* __restrict__ kap_p,
    const float* __restrict__ lck_p, const float* __restrict__ lcz_p,
    float* __restrict__ out, int B, int NC, int ns)
{
    // [buf][64 rows * 16 dwords]  (hi plane only)
    __shared__ __align__(16) uint32_t smu[2 * 1024];
    __shared__ float s_red[8];
    __shared__ int   s_last;

    const int tid  = threadIdx.x;
    const int wid  = tid >> 5;
    const int lane = tid & 31;
    const int g    = lane >> 2;
    const int l4   = lane & 3;

    if (tid == 0) s_last = 0;

    const float ke   = __ldg(kap_p) * L2E;
    const float bias = -ke;

    // ---- parent mu_hat for this warp's 16 z rows (all share one parent;
    //      zr mod 32 in {0,16} so the 16 rows never straddle a parent) ----
    const int zr = blockIdx.x * 128 + wid * 16;
    float mh = 0.f;
    const bool uniform_parent = (ns == 32);
    if (uniform_parent) {
        float m = __ldg(mu + (size_t)(zr >> 5) * DZ + lane);
        float ss = m * m;
        #pragma unroll
        for (int o = 16; o > 0; o >>= 1) ss += __shfl_xor_sync(0xFFFFFFFFu, ss, o);
        float r = rsqrtf(ss);
        r = r * fmaf(-0.5f * ss * r, r, 1.5f);
        mh = m * r;
    }

    // ---- A fragments (fp16 hi/lo split, one m16 tile) + parent dots ----
    uint32_t ahi[2][4], alo[2][4];
    float dq[2] = {0.f, 0.f};
    {
        const int r0 = zr + g;
        const int r1 = r0 + 8;
        #pragma unroll
        for (int e = 0; e < 4; e++) {
            const int c2 = l4 + 4 * e;
            float2 f0 = __ldg((const float2*)(z + (size_t)r0 * DZ) + c2);
            float2 f1 = __ldg((const float2*)(z + (size_t)r1 * DZ) + c2);
            float mv0 = __shfl_sync(0xFFFFFFFFu, mh, (2 * c2) & 31);
            float mv1 = __shfl_sync(0xFFFFFFFFu, mh, (2 * c2 + 1) & 31);
            dq[0] += mv0 * f0.x + mv1 * f0.y;
            dq[1] += mv0 * f1.x + mv1 * f1.y;
            __half2 h0 = __floats2half2_rn(f0.x, f0.y);
            __half2 h1 = __floats2half2_rn(f1.x, f1.y);
            __half2 e0 = __floats2half2_rn(f0.x - __half2float(__low2half(h0)),
                                           f0.y - __half2float(__high2half(h0)));
            __half2 e1 = __floats2half2_rn(f1.x - __half2float(__low2half(h1)),
                                           f1.y - __half2float(__high2half(h1)));
            const int kb = e >> 1, half = e & 1;
            ahi[kb][half * 2 + 0] = *(uint32_t*)&h0;
            ahi[kb][half * 2 + 1] = *(uint32_t*)&h1;
            alo[kb][half * 2 + 0] = *(uint32_t*)&e0;
            alo[kb][half * 2 + 1] = *(uint32_t*)&e1;
        }
    }
    // single conservative threshold: min over the tile's two row thresholds
    // (raw logit scale: ke*dot_parent - 41); min -> only extra accepts.
    __half thrmin;
    {
        float d0 = dq[0], d1 = dq[1];
        d0 += __shfl_xor_sync(0xFFFFFFFFu, d0, 1);
        d0 += __shfl_xor_sync(0xFFFFFFFFu, d0, 2);
        d1 += __shfl_xor_sync(0xFFFFFFFFu, d1, 1);
        d1 += __shfl_xor_sync(0xFFFFFFFFu, d1, 2);
        float t = uniform_parent ? (ke * fminf(d0, d1) - 41.0f) : -1e30f;
        thrmin = __float2half(t);
    }

    const uint32_t sbase = s2u(smu);
    const uint32_t warp_off = (uint32_t)(g * 64 + l4 * 16);
    const int T = B >> 6;

    auto copy_chunk = [&](int t, int buf) {
        const uint32_t dst = sbase + (uint32_t)buf * 4096u;
        cp16(dst + (uint32_t)tid * 16u, g_mu_hi + (size_t)t * 1024 + tid * 4);
        asm volatile("cp.async.commit_group;" ::: "memory");
    };

    float acc[2] = {0.f, 0.f};

    copy_chunk(0, 0);
    for (int t = 0; t < T; t++) {
        const int buf = t & 1;
        if (t + 1 < T) {
            copy_chunk(t + 1, buf ^ 1);
            asm volatile("cp.async.wait_group 1;" ::: "memory");
        } else {
            asm volatile("cp.async.wait_group 0;" ::: "memory");
        }
        __syncthreads();

        const uint32_t hib = sbase + (uint32_t)buf * 4096u + warp_off;
        // lo plane row base for this chunk (global), thread-fixed part folded
        const uint32_t* lo_base = g_mu_lo + ((size_t)t * 64 + g) * 16 + l4 * 4;

        #pragma unroll
        for (int noff = 0; noff < 64; noff += 8) {
            // ONE LDS.128: full hi B-fragment (k-pairs l4, l4+4, l4+8, l4+12)
            uint32_t Bh[4];
            asm volatile("ld.shared.v4.u32 {%0,%1,%2,%3}, [%4];"
                         : "=r"(Bh[0]), "=r"(Bh[1]), "=r"(Bh[2]), "=r"(Bh[3])
                         : "r"(hib + (uint32_t)noff * 64u));

            // fp16-accum prefilter (raw logits)
            uint32_t D[2] = {0u, 0u};
            mma16h(D, ahi[0], Bh[0], Bh[1]);
            mma16h(D, ahi[1], Bh[2], Bh[3]);

            __half2 m2 = __hmax2(*(__half2*)&D[0], *(__half2*)&D[1]);
            __half  mx = __hmax(__low2half(m2), __high2half(m2));

            if (__any_sync(0xFFFFFFFFu, __hgt(mx, thrmin))) {
                // lo B-fragment straight from global (L2-resident, coalesced)
                uint4 blv = __ldg((const uint4*)(lo_base + (size_t)noff * 16));
                float c[4] = {bias, bias, bias, bias};
                mma16(c, ahi[0], Bh[0], Bh[1]);
                mma16(c, ahi[1], Bh[2], Bh[3]);
                mma16(c, alo[0], Bh[0], Bh[1]);
                mma16(c, alo[1], Bh[2], Bh[3]);
                mma16(c, ahi[0], blv.x, blv.y);
                mma16(c, ahi[1], blv.z, blv.w);
                acc[0] += ex2f(c[0]) + ex2f(c[1]);   // row g
                acc[1] += ex2f(c[2]) + ex2f(c[3]);   // row g+8
            }
        }
        __syncthreads();
    }

    // ---- quad reduce (mu cols), ln, butterfly over the 8 g-groups ----
    #pragma unroll
    for (int q = 0; q < 2; q++) {
        acc[q] += __shfl_xor_sync(0xFFFFFFFFu, acc[q], 1);
        acc[q] += __shfl_xor_sync(0xFFFFFFFFu, acc[q], 2);
    }
    float lv = logf(fmaxf(acc[0], 1e-38f)) + logf(fmaxf(acc[1], 1e-38f));
    #pragma unroll
    for (int o = 4; o < 32; o <<= 1)
        lv += __shfl_xor_sync(0xFFFFFFFFu, lv, o);

    if (lane == 0) s_red[wid] = lv;
    __syncthreads();
    if (tid == 0) {
        float tot = 0.f;
        #pragma unroll
        for (int w = 0; w < 8; w++) tot += s_red[w];
        g_partials[blockIdx.x] = tot;
        __threadfence();
        int tk = atomicAdd(&g_ticket, 1);
        s_last = (tk == (int)gridDim.x - 1);
        if (s_last) g_ticket = 0;           // reset for next graph replay
    }
    __syncthreads();

    // ---- last block: deterministic fixed-order final reduction ----
    if (s_last) {
        volatile float* vp = g_partials;
        float v = 0.f;
        for (int i = tid; i < (int)gridDim.x; i += blockDim.x) v += vp[i];
        #pragma unroll
        for (int o = 16; o > 0; o >>= 1) v += __shfl_xor_sync(0xFFFFFFFFu, v, o);
        if (lane == 0) s_red[wid] = v;
        __syncthreads();
        if (tid == 0) {
            float tot = 0.f;
            #pragma unroll
            for (int w = 0; w < 8; w++) tot += s_red[w];
            float okl = __ldg(lck_p) + __ldg(kap_p)
                      - logf((float)B) - __ldg(lcz_p)
                      + tot / (float)NC;
            out[0] = okl;
        }
    }
}

// ---------------------------------------------------------------------------
extern "C" void kernel_launch(void* const* d_in, const int* in_sizes, int n_in,
                              void* d_out, int out_size)
{
    const float* mu  = (const float*)d_in[0];
    const float* z   = (const float*)d_in[1];
    const float* kap = (const float*)d_in[2];
    const float* lck = (const float*)d_in[3];
    const float* lcz = (const float*)d_in[4];

    const int B  = in_sizes[0] / DZ;    // 2048
    const int NC = in_sizes[1] / DZ;    // 65536 sample vectors
    const int ns = NC / B;              // samples per mu (32)

    vmf_prep_mu<<<(B + 7) / 8, 256>>>(mu, kap, B);

    const int grid = NC / 128;          // 128 z rows per block -> 512 CTAs
    vmf_main<<<grid, 256>>>(mu, z, kap, lck, lcz, (float*)d_out, B, NC, ns);
}

// round 15
// speedup vs baseline: 1.2865x; 1.2865x over previous
#include <cuda_runtime.h>
#include <cuda_fp16.h>
#include <cstdint>

#define DZ 32
#define L2E 1.4426950408889634f

// ---------------------------------------------------------------------------
// Static device scratch (no runtime allocation allowed)
// g_mu_hi: per mu row n: 16 dwords (half2 k-pairs), position 4*(p&3)+(p>>2)
// holds k-pair p -> thread l4 reads pairs {l4,l4+4,l4+8,l4+12} as one
// contiguous 16-byte LDG.128. Values: w = mu_hat*kappa*log2e in fp16.
// (mu lo-residual dropped: its cross term is ~4.5e-3 log2 units RMS,
//  averaging to ~1e-5 absolute on the final mean -> far under tolerance.)
// ---------------------------------------------------------------------------
__device__ uint32_t g_mu_hi[4096 * 16];
__device__ float g_partials[1024];
__device__ int   g_ticket;            // zero-init; reset by last block each run

static __device__ __forceinline__ float ex2f(float x) {
    float r; asm("ex2.approx.f32 %0, %1;" : "=f"(r) : "f"(x)); return r;
}
// m16n8k16 fp16 MMA, f32 accumulate
static __device__ __forceinline__ void mma16(float* d, const uint32_t* a,
                                             uint32_t b0, uint32_t b1) {
    asm volatile(
        "mma.sync.aligned.m16n8k16.row.col.f32.f16.f16.f32 "
        "{%0,%1,%2,%3},{%4,%5,%6,%7},{%8,%9},{%0,%1,%2,%3};"
        : "+f"(d[0]), "+f"(d[1]), "+f"(d[2]), "+f"(d[3])
        : "r"(a[0]), "r"(a[1]), "r"(a[2]), "r"(a[3]), "r"(b0), "r"(b1));
}
// m16n8k16 fp16 MMA, fp16 accumulate (prefilter)
static __device__ __forceinline__ void mma16h(uint32_t* d, const uint32_t* a,
                                              uint32_t b0, uint32_t b1) {
    asm volatile(
        "mma.sync.aligned.m16n8k16.row.col.f16.f16.f16.f16 "
        "{%0,%1},{%2,%3,%4,%5},{%6,%7},{%0,%1};"
        : "+r"(d[0]), "+r"(d[1])
        : "r"(a[0]), "r"(a[1]), "r"(a[2]), "r"(a[3]), "r"(b0), "r"(b1));
}

// ---------------------------------------------------------------------------
// Prep: normalize mu, scale by kappa*log2e, fp16, store hi plane with the
// k-pair interleave. One warp per row.
// ---------------------------------------------------------------------------
__global__ void vmf_prep_mu(const float* __restrict__ mu,
                            const float* __restrict__ kap_p, int B)
{
    const int n = (blockIdx.x * blockDim.x + threadIdx.x) >> 5;
    const int k = threadIdx.x & 31;
    if (n >= B) return;

    float v = __ldg(mu + (size_t)n * DZ + k);
    float ss = v * v;
    #pragma unroll
    for (int o = 16; o > 0; o >>= 1) ss += __shfl_xor_sync(0xFFFFFFFFu, ss, o);
    float r = rsqrtf(ss);
    r = r * fmaf(-0.5f * ss * r, r, 1.5f);           // Newton -> ~1e-7 rel
    float w = v * r * (__ldg(kap_p) * L2E);

    uint32_t hs = (uint32_t)__half_as_ushort(__float2half_rn(w));
    uint32_t h0 = __shfl_sync(0xFFFFFFFFu, hs, (k * 2) & 31);
    uint32_t h1 = __shfl_sync(0xFFFFFFFFu, hs, (k * 2 + 1) & 31);
    if (k < 16) {
        const int pos = 4 * (k & 3) + (k >> 2);      // k-pair interleave
        g_mu_hi[n * 16 + pos] = h0 | (h1 << 16);
    }
}

// ---------------------------------------------------------------------------
// Main: 128 z rows/CTA (8 warps x ONE m16 tile each), grid 512. NO smem
// tiling, NO barriers in the main loop: each warp streams the mu hi-plane
// (128KB, L1-resident, same walk order chip-wide) via coalesced LDG.128.
// Hot path per 16x8 block: LDG.128 + 2 fp16-accum MMAs + max + vote.
// Accepted (~6%): 4 f32-accum MMAs (hi*hi + zlo*hi) + ex2-accumulate.
// Last block reduces partials -> out.
// ---------------------------------------------------------------------------
__global__ void __launch_bounds__(256, 4) vmf_main(
    const float* __restrict__ mu, const float* __restrict__ z,
    const float* __restrict__ kap_p,
    const float* __restrict__ lck_p, const float* __restrict__ lcz_p,
    float* __restrict__ out, int B, int NC, int ns)
{
    __shared__ float s_red[8];
    __shared__ int   s_last;

    const int tid  = threadIdx.x;
    const int wid  = tid >> 5;
    const int lane = tid & 31;
    const int g    = lane >> 2;
    const int l4   = lane & 3;

    if (tid == 0) s_last = 0;

    const float ke   = __ldg(kap_p) * L2E;
    const float bias = -ke;

    // ---- parent mu_hat for this warp's 16 z rows (all share one parent;
    //      zr mod 32 in {0,16} so the 16 rows never straddle a parent) ----
    const int zr = blockIdx.x * 128 + wid * 16;
    float mh = 0.f;
    const bool uniform_parent = (ns == 32);
    if (uniform_parent) {
        float m = __ldg(mu + (size_t)(zr >> 5) * DZ + lane);
        float ss = m * m;
        #pragma unroll
        for (int o = 16; o > 0; o >>= 1) ss += __shfl_xor_sync(0xFFFFFFFFu, ss, o);
        float r = rsqrtf(ss);
        r = r * fmaf(-0.5f * ss * r, r, 1.5f);
        mh = m * r;
    }

    // ---- A fragments (fp16 hi/lo split of z, one m16 tile) + parent dots ----
    uint32_t ahi[2][4], alo[2][4];
    float dq[2] = {0.f, 0.f};
    {
        const int r0 = zr + g;
        const int r1 = r0 + 8;
        #pragma unroll
        for (int e = 0; e < 4; e++) {
            const int c2 = l4 + 4 * e;
            float2 f0 = __ldg((const float2*)(z + (size_t)r0 * DZ) + c2);
            float2 f1 = __ldg((const float2*)(z + (size_t)r1 * DZ) + c2);
            float mv0 = __shfl_sync(0xFFFFFFFFu, mh, (2 * c2) & 31);
            float mv1 = __shfl_sync(0xFFFFFFFFu, mh, (2 * c2 + 1) & 31);
            dq[0] += mv0 * f0.x + mv1 * f0.y;
            dq[1] += mv0 * f1.x + mv1 * f1.y;
            __half2 h0 = __floats2half2_rn(f0.x, f0.y);
            __half2 h1 = __floats2half2_rn(f1.x, f1.y);
            __half2 e0 = __floats2half2_rn(f0.x - __half2float(__low2half(h0)),
                                           f0.y - __half2float(__high2half(h0)));
            __half2 e1 = __floats2half2_rn(f1.x - __half2float(__low2half(h1)),
                                           f1.y - __half2float(__high2half(h1)));
            const int kb = e >> 1, half = e & 1;
            ahi[kb][half * 2 + 0] = *(uint32_t*)&h0;
            ahi[kb][half * 2 + 1] = *(uint32_t*)&h1;
            alo[kb][half * 2 + 0] = *(uint32_t*)&e0;
            alo[kb][half * 2 + 1] = *(uint32_t*)&e1;
        }
    }
    // per-row thresholds (raw logit scale: ke*dot_parent - 41), as half
    __half thrh[2];
    #pragma unroll
    for (int q = 0; q < 2; q++) {
        float d = dq[q];
        d += __shfl_xor_sync(0xFFFFFFFFu, d, 1);
        d += __shfl_xor_sync(0xFFFFFFFFu, d, 2);
        thrh[q] = __float2half(uniform_parent ? (ke * d - 41.0f) : -1e30f);
    }

    // ---- barrier-free mainloop: stream mu hi-plane via LDG.128 ----
    const uint4* __restrict__ mu_base =
        (const uint4*)(g_mu_hi + (size_t)g * 16 + (size_t)l4 * 4);
    // row n advances by 8 per iter -> +8*16 dwords = +32 uint4

    float acc[2] = {0.f, 0.f};

    #pragma unroll 8
    for (int n = 0; n < B; n += 8) {
        const uint4 bh = __ldg(mu_base + (size_t)n * 4);

        // fp16-accum prefilter (raw logits)
        uint32_t D[2] = {0u, 0u};
        mma16h(D, ahi[0], bh.x, bh.y);
        mma16h(D, ahi[1], bh.z, bh.w);

        __half2 m2 = __hmax2(*(__half2*)&D[0], *(__half2*)&D[1]);
        bool p = __hgt(__low2half(m2),  thrh[0]) |
                 __hgt(__high2half(m2), thrh[1]);

        if (__any_sync(0xFFFFFFFFu, p)) {
            float c[4] = {bias, bias, bias, bias};
            mma16(c, ahi[0], bh.x, bh.y);
            mma16(c, ahi[1], bh.z, bh.w);
            mma16(c, alo[0], bh.x, bh.y);
            mma16(c, alo[1], bh.z, bh.w);
            acc[0] += ex2f(c[0]) + ex2f(c[1]);   // row g
            acc[1] += ex2f(c[2]) + ex2f(c[3]);   // row g+8
        }
    }

    // ---- quad reduce (mu cols), ln, butterfly over the 8 g-groups ----
    #pragma unroll
    for (int q = 0; q < 2; q++) {
        acc[q] += __shfl_xor_sync(0xFFFFFFFFu, acc[q], 1);
        acc[q] += __shfl_xor_sync(0xFFFFFFFFu, acc[q], 2);
    }
    float lv = logf(fmaxf(acc[0], 1e-38f)) + logf(fmaxf(acc[1], 1e-38f));
    #pragma unroll
    for (int o = 4; o < 32; o <<= 1)
        lv += __shfl_xor_sync(0xFFFFFFFFu, lv, o);

    if (lane == 0) s_red[wid] = lv;
    __syncthreads();
    if (tid == 0) {
        float tot = 0.f;
        #pragma unroll
        for (int w = 0; w < 8; w++) tot += s_red[w];
        g_partials[blockIdx.x] = tot;
        __threadfence();
        int tk = atomicAdd(&g_ticket, 1);
        s_last = (tk == (int)gridDim.x - 1);
        if (s_last) g_ticket = 0;           // reset for next graph replay
    }
    __syncthreads();

    // ---- last block: deterministic fixed-order final reduction ----
    if (s_last) {
        volatile float* vp = g_partials;
        float v = 0.f;
        for (int i = tid; i < (int)gridDim.x; i += blockDim.x) v += vp[i];
        #pragma unroll
        for (int o = 16; o > 0; o >>= 1) v += __shfl_xor_sync(0xFFFFFFFFu, v, o);
        if (lane == 0) s_red[wid] = v;
        __syncthreads();
        if (tid == 0) {
            float tot = 0.f;
            #pragma unroll
            for (int w = 0; w < 8; w++) tot += s_red[w];
            float okl = __ldg(lck_p) + __ldg(kap_p)
                      - logf((float)B) - __ldg(lcz_p)
                      + tot / (float)NC;
            out[0] = okl;
        }
    }
}

// ---------------------------------------------------------------------------
extern "C" void kernel_launch(void* const* d_in, const int* in_sizes, int n_in,
                              void* d_out, int out_size)
{
    const float* mu  = (const float*)d_in[0];
    const float* z   = (const float*)d_in[1];
    const float* kap = (const float*)d_in[2];
    const float* lck = (const float*)d_in[3];
    const float* lcz = (const float*)d_in[4];

    const int B  = in_sizes[0] / DZ;    // 2048
    const int NC = in_sizes[1] / DZ;    // 65536 sample vectors
    const int ns = NC / B;              // samples per mu (32)

    vmf_prep_mu<<<(B + 7) / 8, 256>>>(mu, kap, B);

    const int grid = NC / 128;          // 128 z rows per block -> 512 CTAs
    vmf_main<<<grid, 256>>>(mu, z, kap, lck, lcz, (float*)d_out, B, NC, ns);
}